// round 16
// baseline (speedup 1.0000x reference)
#include <cuda_runtime.h>
#include <cuda_bf16.h>
#include <cuda_fp16.h>
#include <math.h>
#include <stdint.h>

#define D_MODEL 2048
#define N_HEADS 32
#define N_KV    8
#define HD      64
#define SEQ     2048
#define BATCH   2
#define NTOK    (BATCH*SEQ)      /* 4096 */
#define QDIM    (N_HEADS*HD)     /* 2048 */
#define KVDIM   (N_KV*HD)        /* 512  */
#define QKVDIM  (QDIM + 2*KVDIM) /* 3072 */
#define ROPE_BASE 500000.0f
#define SCALE_L2E 0.1803368801111204f   /* 0.125 * log2(e) */

/* ---------------- static device scratch ---------------- */
__device__ float g_cos[SEQ*(HD/2)];
__device__ float g_sin[SEQ*(HD/2)];

/* GEMM operands: single fp16 */
__device__ __half g_x  [NTOK*D_MODEL];
__device__ __half g_wb [QKVDIM*D_MODEL];   /* packed Wq|Wk|Wv, [N,K] */
__device__ __half g_wo [D_MODEL*QDIM];
__device__ __half g_ao [NTOK*QDIM];        /* attention out */

/* attention operands (single fp16; q pre-scaled by 0.125*log2e) */
__device__ __half g_qf [NTOK*QDIM];
__device__ __half g_kf [NTOK*KVDIM];
__device__ __half g_vf [NTOK*KVDIM];

/* ---------------- PTX helpers ---------------- */
__device__ __forceinline__ uint32_t smem_u32(const void* p) {
    uint32_t a;
    asm("{ .reg .u64 t; cvta.to.shared.u64 t, %1; cvt.u32.u64 %0, t; }" : "=r"(a) : "l"(p));
    return a;
}
__device__ __forceinline__ void cp16(uint32_t saddr, const void* g) {
    asm volatile("cp.async.cg.shared.global [%0], [%1], 16;" :: "r"(saddr), "l"(g));
}
__device__ __forceinline__ void cp_commit() { asm volatile("cp.async.commit_group;" ::: "memory"); }
__device__ __forceinline__ void cp_wait0()  { asm volatile("cp.async.wait_group 0;"  ::: "memory"); }
__device__ __forceinline__ void cp_wait1()  { asm volatile("cp.async.wait_group 1;"  ::: "memory"); }

__device__ __forceinline__ void ldmx4(uint32_t* r, uint32_t addr) {
    asm volatile("ldmatrix.sync.aligned.m8n8.x4.shared.b16 {%0,%1,%2,%3}, [%4];"
                 : "=r"(r[0]), "=r"(r[1]), "=r"(r[2]), "=r"(r[3]) : "r"(addr));
}
__device__ __forceinline__ void ldmx4t(uint32_t* r, uint32_t addr) {
    asm volatile("ldmatrix.sync.aligned.m8n8.x4.trans.shared.b16 {%0,%1,%2,%3}, [%4];"
                 : "=r"(r[0]), "=r"(r[1]), "=r"(r[2]), "=r"(r[3]) : "r"(addr));
}
__device__ __forceinline__ void mma16816h(float* d, const uint32_t* a, const uint32_t* b) {
    asm volatile(
        "mma.sync.aligned.m16n8k16.row.col.f32.f16.f16.f32 "
        "{%0,%1,%2,%3}, {%4,%5,%6,%7}, {%8,%9}, {%0,%1,%2,%3};"
        : "+f"(d[0]), "+f"(d[1]), "+f"(d[2]), "+f"(d[3])
        : "r"(a[0]), "r"(a[1]), "r"(a[2]), "r"(a[3]), "r"(b[0]), "r"(b[1]));
}
__device__ __forceinline__ float ex2(float x) {
    float y; asm("ex2.approx.f32 %0, %1;" : "=f"(y) : "f"(x)); return y;
}
__device__ __forceinline__ uint32_t pkh(float a, float b) {
    __half2 t = __floats2half2_rn(a, b);
    return *(uint32_t*)&t;
}

/* ---------------- fused prep kernel ----------------
 * block ranges: [0,256) rope | [256,8448) convx | [8448,14592) tconv_qkv
 *               | [14592,18688) tconv_wo
 */
#define PREP_BLOCKS (256 + 8192 + 6144 + 4096)

__global__ __launch_bounds__(256)
void prep_kernel(const float* __restrict__ x,
                 const float* __restrict__ Wq, const float* __restrict__ Wk,
                 const float* __restrict__ Wv, const float* __restrict__ Wo) {
    __shared__ float t[32][33];
    int bi = blockIdx.x, tid = threadIdx.x;
    if (bi < 256) {
        int i = bi * 256 + tid;
        if (i < SEQ * (HD/2)) {
            int tt = i >> 5;
            int j = i & 31;
            float exv = (float)j * (1.0f / 32.0f);
            float inv = powf(ROPE_BASE, -exv);
            float ang = (float)tt * inv;
            float s, c;
            sincosf(ang, &s, &c);
            g_cos[i] = c;
            g_sin[i] = s;
        }
    } else if (bi < 8448) {
        int i = (bi - 256) * 256 + tid;
        float4 v = ((const float4*)x)[i];
        __half h[4] = { __float2half_rn(v.x), __float2half_rn(v.y),
                        __float2half_rn(v.z), __float2half_rn(v.w) };
        ((uint2*)g_x)[i] = *(uint2*)h;
    } else if (bi < 14592) {
        int j = bi - 8448;
        int np = (j % 96) * 32;
        int k0 = (j / 96) * 32;
        const float* W;
        int N, off;
        if (np < QDIM)              { W = Wq; N = QDIM;  off = 0; }
        else if (np < QDIM + KVDIM) { W = Wk; N = KVDIM; off = QDIM; }
        else                        { W = Wv; N = KVDIM; off = QDIM + KVDIM; }
        int n0 = np - off;
        int tx = tid & 31, ty = tid >> 5;
#pragma unroll
        for (int i = 0; i < 32; i += 8)
            t[ty + i][tx] = W[(size_t)(k0 + ty + i) * N + n0 + tx];
        __syncthreads();
#pragma unroll
        for (int i = 0; i < 32; i += 8)
            g_wb[(size_t)(np + ty + i) * D_MODEL + k0 + tx] = __float2half_rn(t[tx][ty + i]);
    } else {
        int j = bi - 14592;
        int n0 = (j % 64) * 32;
        int k0 = (j / 64) * 32;
        int tx = tid & 31, ty = tid >> 5;
#pragma unroll
        for (int i = 0; i < 32; i += 8)
            t[ty + i][tx] = Wo[(size_t)(k0 + ty + i) * D_MODEL + n0 + tx];
        __syncthreads();
#pragma unroll
        for (int i = 0; i < 32; i += 8)
            g_wo[(size_t)(n0 + ty + i) * QDIM + k0 + tx] = __float2half_rn(t[tx][ty + i]);
    }
}

/* ---------------- single-fp16 GEMM mainloop macro ---------------- */
#define TILE_B   10240
#define STAGE_B  (2*TILE_B)
#define GEMM_SMEM (2*STAGE_B)     /* 40960 */

#define GEMM_MAIN(Ap, Bp, Kdim)                                                   \
    extern __shared__ char smem[];                                                \
    uint32_t sb = smem_u32(smem);                                                 \
    int tid = threadIdx.x, lane = tid & 31, wid = tid >> 5;                       \
    int wm = wid & 1, wn = wid >> 1;                                              \
    int bm = blockIdx.y * 128, bn = blockIdx.x * 128;                             \
    int lr = tid >> 2;                                                            \
    int lc = tid & 3;                                                             \
    const __half* gA1 = (Ap) + (size_t)(bm + lr) * (Kdim) + lc * 8;               \
    const __half* gB1 = (Bp) + (size_t)(bn + lr) * (Kdim) + lc * 8;               \
    size_t rstep = (size_t)32 * (Kdim);                                           \
    uint32_t soff = lr * 80 + lc * 16;                                            \
    float acc[4][8][4];                                                           \
    _Pragma("unroll")                                                             \
    for (int i = 0; i < 4; i++)                                                   \
        _Pragma("unroll")                                                         \
        for (int j = 0; j < 8; j++)                                               \
            _Pragma("unroll")                                                     \
            for (int t = 0; t < 4; t++) acc[i][j][t] = 0.f;                       \
    int nkt = (Kdim) >> 5;                                                        \
    {                                                                             \
        _Pragma("unroll")                                                         \
        for (int r = 0; r < 4; r++) {                                             \
            uint32_t so = sb + soff + r * 2560;                                   \
            cp16(so,          gA1 + r * rstep);                                   \
            cp16(so + TILE_B, gB1 + r * rstep);                                   \
        }                                                                         \
    }                                                                             \
    cp_commit(); cp_wait0(); __syncthreads();                                     \
    uint32_t aBase = 2 * ((uint32_t)(wm * 64 + (lane & 15)) * 40 + ((lane >> 4) << 3)); \
    uint32_t bBase = 2 * ((uint32_t)(wn * 64 + (lane & 7) + ((lane >> 4) << 3)) * 40 + (lane & 8)); \
    for (int kt = 0; kt < nkt; kt++) {                                            \
        if (kt + 1 < nkt) {                                                       \
            int koff = (kt + 1) << 5;                                             \
            uint32_t st = sb + ((kt + 1) & 1) * STAGE_B;                          \
            _Pragma("unroll")                                                     \
            for (int r = 0; r < 4; r++) {                                         \
                uint32_t so = st + soff + r * 2560;                               \
                cp16(so,          gA1 + r * rstep + koff);                        \
                cp16(so + TILE_B, gB1 + r * rstep + koff);                        \
            }                                                                     \
        }                                                                         \
        cp_commit();                                                              \
        uint32_t base = sb + (kt & 1) * STAGE_B;                                  \
        _Pragma("unroll")                                                         \
        for (int kb = 0; kb < 32; kb += 16) {                                     \
            uint32_t af[4][4], bf[4][4];                                          \
            _Pragma("unroll")                                                     \
            for (int mt = 0; mt < 4; mt++)                                        \
                ldmx4(af[mt], base + aBase + 2 * (mt * 16 * 40 + kb));            \
            _Pragma("unroll")                                                     \
            for (int g = 0; g < 4; g++)                                           \
                ldmx4(bf[g], base + TILE_B + bBase + 2 * (g * 16 * 40 + kb));     \
            _Pragma("unroll")                                                     \
            for (int mt = 0; mt < 4; mt++)                                        \
                _Pragma("unroll")                                                 \
                for (int nt = 0; nt < 8; nt++)                                    \
                    mma16816h(acc[mt][nt], af[mt], &bf[nt >> 1][(nt & 1) * 2]);   \
        }                                                                         \
        cp_wait0();                                                               \
        __syncthreads();                                                          \
    }

/* ---------------- Wo GEMM ---------------- */
__global__ __launch_bounds__(128, 2)
void hmma_gemm_wo(float* __restrict__ C) {
    GEMM_MAIN(g_ao, g_wo, QDIM)
    int er = lane >> 2, ec = (lane & 3) * 2;
#pragma unroll
    for (int mt = 0; mt < 4; mt++)
#pragma unroll
        for (int nt = 0; nt < 8; nt++) {
            int row = bm + wm * 64 + mt * 16 + er;
            int col = bn + wn * 64 + nt * 8 + ec;
            *(float2*)(C + (size_t)row * D_MODEL + col) =
                make_float2(acc[mt][nt][0], acc[mt][nt][1]);
            *(float2*)(C + (size_t)(row + 8) * D_MODEL + col) =
                make_float2(acc[mt][nt][2], acc[mt][nt][3]);
        }
}

/* ---------------- QKV GEMM with fused RoPE + fp16 epilogue -------------- */
__global__ __launch_bounds__(128, 2)
void hmma_gemm_qkv() {
    GEMM_MAIN(g_x, g_wb, D_MODEL)
    int er = lane >> 2, ec = (lane & 3) * 2;
    int head = (bn + wn * 64) >> 6;           /* 0..47 */
    if (head < N_HEADS + N_KV) {
        bool isq = head < N_HEADS;
        float scl = isq ? SCALE_L2E : 1.0f;    /* fold softmax scale into q */
        int dim  = isq ? QDIM : KVDIM;
        int hcol = (isq ? head : head - N_HEADS) * HD;
        __half* dst = isq ? g_qf : g_kf;
#pragma unroll
        for (int mt = 0; mt < 4; mt++) {
            int row = bm + wm * 64 + mt * 16 + er;
#pragma unroll
            for (int hr = 0; hr < 2; hr++) {
                int tok = row + hr * 8;
                int s = tok & (SEQ - 1);
                int e0 = hr * 2;
#pragma unroll
                for (int nt = 0; nt < 4; nt++) {
                    int j = nt * 8 + ec;
                    float c0 = g_cos[s*32 + j],   c1 = g_cos[s*32 + j + 1];
                    float n0 = g_sin[s*32 + j],   n1 = g_sin[s*32 + j + 1];
                    float x1a = acc[mt][nt][e0],     x1b = acc[mt][nt][e0+1];
                    float x2a = acc[mt][nt+4][e0],   x2b = acc[mt][nt+4][e0+1];
                    size_t o1 = (size_t)tok * dim + hcol + j;
                    *(uint32_t*)(dst + o1)      = pkh((x1a*c0 - x2a*n0)*scl, (x1b*c1 - x2b*n1)*scl);
                    *(uint32_t*)(dst + o1 + 32) = pkh((x2a*c0 + x1a*n0)*scl, (x2b*c1 + x1b*n1)*scl);
                }
            }
        }
    } else {
        int hcol = (head - N_HEADS - N_KV) * HD;
#pragma unroll
        for (int mt = 0; mt < 4; mt++) {
            int row = bm + wm * 64 + mt * 16 + er;
#pragma unroll
            for (int nt = 0; nt < 8; nt++) {
                int jj = nt * 8 + ec;
                *(uint32_t*)(g_vf + (size_t)row * KVDIM + hcol + jj) =
                    pkh(acc[mt][nt][0], acc[mt][nt][1]);
                *(uint32_t*)(g_vf + (size_t)(row + 8) * KVDIM + hcol + jj) =
                    pkh(acc[mt][nt][2], acc[mt][nt][3]);
            }
        }
    }
}

/* ---------------- fp16 flash attention: 2 heads/CTA, 512 threads --------
 * 16 warps: hh = wid>>3 (head of pair), wq = wid&3 (16-row group),
 * wk = (wid>>2)&1 (kv half). KV staged once per block, shared by both heads.
 * Double-buffered: stage = K(9216)|V(9216).
 */
#define AST 18432
#define ATTN_SMEM (2*AST)

__global__ __launch_bounds__(512)
void attn_kernel(const int* __restrict__ cu) {
    extern __shared__ char smem[];
    uint32_t sb = smem_u32(smem);
    int qb = blockIdx.x, hp = blockIdx.y, b = blockIdx.z;
    int kvh = hp >> 1;
    int tid = threadIdx.x, lane = tid & 31, wid = tid >> 5;
    int hh = wid >> 3, wq = wid & 3, wk = (wid >> 2) & 1;
    int h = hp * 2 + hh;

    int b0 = min(max(cu[b*4+0], 0), SEQ);
    int b1 = min(max(cu[b*4+1], 0), SEQ);
    int b2 = min(max(cu[b*4+2], 0), SEQ);
    int b3 = min(max(cu[b*4+3], 0), SEQ);

    int p0 = qb * 64;
    int s_start = 0;
    if (b0 <= p0) s_start = b0;
    if (b1 <= p0) s_start = max(s_start, b1);
    if (b2 <= p0) s_start = max(s_start, b2);
    if (b3 <= p0) s_start = max(s_start, b3);
    int kb0 = s_start >> 6;

    /* stage Q for both heads (2 x 64 x 64 fp16) into stage0 */
#pragma unroll
    for (int i = 0; i < 2; i++) {
        int idx = tid + i * 512;           /* 0..1023 */
        int hh_ = idx >> 9;
        int rem = idx & 511;
        int row = rem >> 3, c = rem & 7;
        cp16(sb + hh_*9216 + row*144 + c*16,
             g_qf + (size_t)(b*SEQ + p0 + row) * QDIM + (hp*2 + hh_)*HD + c*8);
    }
    cp_commit(); cp_wait0(); __syncthreads();

    uint32_t qh[4][4];
#pragma unroll
    for (int kt = 0; kt < 4; kt++) {
        uint32_t off = (uint32_t)(wq*16 + (lane & 15)) * 144 + (kt*16 + ((lane >> 4) << 3)) * 2;
        ldmx4(qh[kt], sb + hh*9216 + off);
    }
    __syncthreads();   /* Q consumed; stages reusable */

    int qp0 = p0 + wq*16 + (lane >> 2);
    int qp1 = qp0 + 8;
    int qsg0 = (b0 <= qp0) + (b1 <= qp0) + (b2 <= qp0) + (b3 <= qp0);
    int qsg1 = (b0 <= qp1) + (b1 <= qp1) + (b2 <= qp1) + (b3 <= qp1);

    float m0 = -INFINITY, m1 = -INFINITY, l0 = 0.f, l1 = 0.f;
    float o[8][4];
#pragma unroll
    for (int nd = 0; nd < 8; nd++)
#pragma unroll
        for (int j = 0; j < 4; j++) o[nd][j] = 0.f;

    int colb = wk*32 + (lane & 3)*2;

#define LOADKV(stb, kb_)                                                          \
    do {                                                                          \
        _Pragma("unroll")                                                         \
        for (int i_ = 0; i_ < 2; i_++) {                                          \
            int idx_ = tid + i_ * 512;                                            \
            int arr_ = idx_ >> 9;                                                 \
            int rem_ = idx_ & 511;                                                \
            int row_ = rem_ >> 3, c_ = rem_ & 7;                                  \
            const __half* src_ = arr_ ? g_vf : g_kf;                              \
            cp16((stb) + arr_*9216 + row_*144 + c_*16,                            \
                 src_ + (size_t)(b*SEQ + (kb_)*64 + row_) * KVDIM + kvh*HD + c_*8);\
        }                                                                         \
    } while (0)

    LOADKV(sb + (kb0 & 1) * AST, kb0);
    cp_commit();

    for (int kb = kb0; kb <= qb; kb++) {
        if (kb < qb) {
            LOADKV(sb + ((kb + 1) & 1) * AST, kb + 1);
            cp_commit();
            cp_wait1();
        } else {
            cp_wait0();
        }
        __syncthreads();
        uint32_t st = sb + (kb & 1) * AST;

        /* S = Q K^T (q pre-scaled: accumulators are base-2 logits) */
        float s[4][4];
#pragma unroll
        for (int nt = 0; nt < 4; nt++)
#pragma unroll
            for (int j = 0; j < 4; j++) s[nt][j] = 0.f;

#pragma unroll
        for (int kt = 0; kt < 4; kt++) {
            uint32_t khf[2][4];
#pragma unroll
            for (int np = 0; np < 2; np++) {
                int mq = lane >> 3, r = lane & 7;
                uint32_t off = (uint32_t)(wk*32 + np*16 + ((mq & 2) ? 8 : 0) + r) * 144
                             + (kt*16 + ((mq & 1) ? 8 : 0)) * 2;
                ldmx4(khf[np], st + off);
            }
#pragma unroll
            for (int nt = 0; nt < 4; nt++)
                mma16816h(s[nt], qh[kt], &khf[nt >> 1][(nt & 1) * 2]);
        }

#pragma unroll
        for (int nt = 0; nt < 4; nt++)
#pragma unroll
            for (int e = 0; e < 2; e++) {
                int kp = kb*64 + colb + nt*8 + e;
                int sk = (b0 <= kp) + (b1 <= kp) + (b2 <= kp) + (b3 <= kp);
                if (kp > qp0 || sk != qsg0) s[nt][e]     = -INFINITY;
                if (kp > qp1 || sk != qsg1) s[nt][2 + e] = -INFINITY;
            }

        float rm0 = -INFINITY, rm1 = -INFINITY;
#pragma unroll
        for (int nt = 0; nt < 4; nt++) {
            rm0 = fmaxf(rm0, fmaxf(s[nt][0], s[nt][1]));
            rm1 = fmaxf(rm1, fmaxf(s[nt][2], s[nt][3]));
        }
        rm0 = fmaxf(rm0, __shfl_xor_sync(0xffffffffu, rm0, 1));
        rm0 = fmaxf(rm0, __shfl_xor_sync(0xffffffffu, rm0, 2));
        rm1 = fmaxf(rm1, __shfl_xor_sync(0xffffffffu, rm1, 1));
        rm1 = fmaxf(rm1, __shfl_xor_sync(0xffffffffu, rm1, 2));
        float mn0 = fmaxf(m0, rm0), mn1 = fmaxf(m1, rm1);
        bool lv0 = mn0 > -INFINITY, lv1 = mn1 > -INFINITY;
        float sc0 = lv0 ? ((m0 > -INFINITY) ? ex2(m0 - mn0) : 0.f) : 1.f;
        float sc1 = lv1 ? ((m1 > -INFINITY) ? ex2(m1 - mn1) : 0.f) : 1.f;

        float p[4][4];
        float rs0 = 0.f, rs1 = 0.f;
#pragma unroll
        for (int nt = 0; nt < 4; nt++) {
#pragma unroll
            for (int e = 0; e < 2; e++) {
                float v0 = lv0 ? ex2(s[nt][e]     - mn0) : 0.f;
                float v1 = lv1 ? ex2(s[nt][2 + e] - mn1) : 0.f;
                p[nt][e] = v0;     rs0 += v0;
                p[nt][2+e] = v1;   rs1 += v1;
            }
        }
        rs0 += __shfl_xor_sync(0xffffffffu, rs0, 1);
        rs0 += __shfl_xor_sync(0xffffffffu, rs0, 2);
        rs1 += __shfl_xor_sync(0xffffffffu, rs1, 1);
        rs1 += __shfl_xor_sync(0xffffffffu, rs1, 2);
        l0 = l0 * sc0 + rs0;  m0 = mn0;
        l1 = l1 * sc1 + rs1;  m1 = mn1;
#pragma unroll
        for (int nd = 0; nd < 8; nd++) {
            o[nd][0] *= sc0; o[nd][1] *= sc0;
            o[nd][2] *= sc1; o[nd][3] *= sc1;
        }

        /* O += P V */
#pragma unroll
        for (int kt2 = 0; kt2 < 2; kt2++) {
            uint32_t pah[4] = { pkh(p[2*kt2][0],   p[2*kt2][1]),
                                pkh(p[2*kt2][2],   p[2*kt2][3]),
                                pkh(p[2*kt2+1][0], p[2*kt2+1][1]),
                                pkh(p[2*kt2+1][2], p[2*kt2+1][3]) };
#pragma unroll
            for (int ndp = 0; ndp < 4; ndp++) {
                int mq = lane >> 3, r = lane & 7;
                uint32_t off = (uint32_t)(wk*32 + kt2*16 + ((mq & 1) ? 8 : 0) + r) * 144
                             + (ndp*16 + ((mq & 2) ? 8 : 0)) * 2;
                uint32_t vh4[4];
                ldmx4t(vh4, st + 9216 + off);
#pragma unroll
                for (int q2 = 0; q2 < 2; q2++)
                    mma16816h(o[ndp*2 + q2], pah, &vh4[q2*2]);
            }
        }
        __syncthreads();
    }
#undef LOADKV

    /* merge kv-halves via smem (per head) */
    float* Osm = (float*)(smem + hh * 17408);        /* 64 x 68 */
    float* msm = (float*)(smem + 34816 + hh * 256);  /* 64 */
    float* lsm = (float*)(smem + 35328 + hh * 256);  /* 64 */
    int rl = wq*16 + (lane >> 2);
    int c2 = (lane & 3)*2;
    if (wk == 1) {
#pragma unroll
        for (int nd = 0; nd < 8; nd++) {
            *(float2*)&Osm[rl*68 + nd*8 + c2]     = make_float2(o[nd][0], o[nd][1]);
            *(float2*)&Osm[(rl+8)*68 + nd*8 + c2] = make_float2(o[nd][2], o[nd][3]);
        }
        if ((lane & 3) == 0) {
            msm[rl] = m0; msm[rl+8] = m1;
            lsm[rl] = l0; lsm[rl+8] = l1;
        }
    }
    __syncthreads();
    if (wk == 0) {
        float pm0 = msm[rl], pm1 = msm[rl+8];
        float pl0 = lsm[rl], pl1 = lsm[rl+8];
        float M0 = fmaxf(m0, pm0), M1 = fmaxf(m1, pm1);
        float sa0 = (m0  > -INFINITY) ? ex2(m0  - M0) : 0.f;
        float sb0 = (pm0 > -INFINITY) ? ex2(pm0 - M0) : 0.f;
        float sa1 = (m1  > -INFINITY) ? ex2(m1  - M1) : 0.f;
        float sb1 = (pm1 > -INFINITY) ? ex2(pm1 - M1) : 0.f;
        float inv0 = 1.f / (l0*sa0 + pl0*sb0);
        float inv1 = 1.f / (l1*sa1 + pl1*sb1);
        size_t r0g = (size_t)(b*SEQ + p0 + rl) * QDIM + h*HD;
        size_t r1g = (size_t)(b*SEQ + p0 + rl + 8) * QDIM + h*HD;
#pragma unroll
        for (int nd = 0; nd < 8; nd++) {
            float v0 = (o[nd][0]*sa0 + Osm[rl*68 + nd*8 + c2]*sb0) * inv0;
            float v1 = (o[nd][1]*sa0 + Osm[rl*68 + nd*8 + c2 + 1]*sb0) * inv0;
            float v2 = (o[nd][2]*sa1 + Osm[(rl+8)*68 + nd*8 + c2]*sb1) * inv1;
            float v3 = (o[nd][3]*sa1 + Osm[(rl+8)*68 + nd*8 + c2 + 1]*sb1) * inv1;
            *(uint32_t*)(g_ao + r0g + nd*8 + c2) = pkh(v0, v1);
            *(uint32_t*)(g_ao + r1g + nd*8 + c2) = pkh(v2, v3);
        }
    }
}

/* ------------------------------------------------------------------ */
extern "C" void kernel_launch(void* const* d_in, const int* in_sizes, int n_in,
                              void* d_out, int out_size) {
    const float* x  = (const float*)d_in[0];
    const int*   cu = (const int*)  d_in[1];
    const float* Wq = (const float*)d_in[2];
    const float* Wk = (const float*)d_in[3];
    const float* Wv = (const float*)d_in[4];
    const float* Wo = (const float*)d_in[5];
    float* out = (float*)d_out;

    cudaFuncSetAttribute(attn_kernel,
                         cudaFuncAttributeMaxDynamicSharedMemorySize, ATTN_SMEM);
    cudaFuncSetAttribute(hmma_gemm_wo,
                         cudaFuncAttributeMaxDynamicSharedMemorySize, GEMM_SMEM);
    cudaFuncSetAttribute(hmma_gemm_qkv,
                         cudaFuncAttributeMaxDynamicSharedMemorySize, GEMM_SMEM);

    /* fused prep (rope table, x->fp16, W transposes) */
    prep_kernel<<<PREP_BLOCKS, 256>>>(x, Wq, Wk, Wv, Wo);

    /* merged QKV projection with fused rope+fp16 epilogue */
    hmma_gemm_qkv<<<dim3(QKVDIM/128, NTOK/128), 128, GEMM_SMEM>>>();

    /* attention: 2 heads per CTA */
    attn_kernel<<<dim3(SEQ/64, N_HEADS/2, BATCH), 512, ATTN_SMEM>>>(cu);

    /* output projection */
    hmma_gemm_wo<<<dim3(D_MODEL/128, NTOK/128), 128, GEMM_SMEM>>>(out);
}